// round 9
// baseline (speedup 1.0000x reference)
#include <cuda_runtime.h>
#include <cuda_bf16.h>
#include <cuda_fp16.h>

#define N_MAX 100000
#define NF 128
#define NH 64
#define NC 16

// Scratch (alloc-free rule: __device__ globals)
__device__ __half g_h0h[N_MAX * NH];   // x @ W1, fp16
__device__ float  g_h1[N_MAX * NH];    // layer-1 aggregate, fp32 accumulator
__device__ __half g_h2h[N_MAX * NC];   // relu(h1) @ W2, fp16

// ---------------- bit-cast helpers -----------------------------------------
__device__ __forceinline__ unsigned int h2_to_u(__half2 h) {
    unsigned int u; memcpy(&u, &h, 4); return u;
}
__device__ __forceinline__ __half2 u_to_h2(unsigned int u) {
    __half2 h; memcpy(&h, &u, 4); return h;
}

// ---------------- packed f32x2 helpers -------------------------------------
__device__ __forceinline__ unsigned long long pk2(float lo, float hi) {
    unsigned long long r;
    asm("mov.b64 %0, {%1, %2};" : "=l"(r) : "f"(lo), "f"(hi));
    return r;
}
__device__ __forceinline__ void fma2(unsigned long long& d,
                                     unsigned long long a, unsigned long long b) {
    asm("fma.rn.f32x2 %0, %1, %2, %0;" : "+l"(d) : "l"(a), "l"(b));
}
__device__ __forceinline__ float2 upk2(unsigned long long v) {
    float2 f;
    asm("mov.b64 {%0, %1}, %2;" : "=f"(f.x), "=f"(f.y) : "l"(v));
    return f;
}

// ---------------------------------------------------------------------------
// GEMM1: h0 = x @ W1 (fp32 math via packed fma.rn.f32x2), store fp16.
// Also zeroes this block's 64 rows of g_h1.
// ---------------------------------------------------------------------------
__global__ void __launch_bounds__(256) gemm1_kernel(
    const float* __restrict__ x, const float* __restrict__ W1, int n)
{
    __shared__ float ws[NF * NH];    // [k][c], 32 KB
    __shared__ float xs[32 * 68];    // [k_local][row]

    int tid = threadIdx.x;
    #pragma unroll
    for (int i = tid; i < NF * NH / 4; i += 256)
        ((float4*)ws)[i] = ((const float4*)W1)[i];

    int row0 = blockIdx.x * 64;

    // fused zeroing of g_h1 rows for this tile
    #pragma unroll
    for (int i = tid; i < 64 * 16; i += 256) {
        int r = i >> 4, j = i & 15;
        int grow = row0 + r;
        if (grow < n)
            *(float4*)&g_h1[grow * NH + j * 4] = make_float4(0.f, 0.f, 0.f, 0.f);
    }

    int tx = tid & 15, ty = tid >> 4;
    int r0 = ty * 4, c0 = tx * 4;
    int kq = tid & 7;
    int lrow = tid >> 3;

    unsigned long long acc[2][4] = {};

    for (int kc = 0; kc < 4; kc++) {
        __syncthreads();
        #pragma unroll
        for (int pass = 0; pass < 2; pass++) {
            int row = lrow + pass * 32;
            int grow = row0 + row;
            float4 v = make_float4(0.f, 0.f, 0.f, 0.f);
            if (grow < n)
                v = *(const float4*)&x[grow * NF + kc * 32 + kq * 4];
            xs[(kq * 4 + 0) * 68 + row] = v.x;
            xs[(kq * 4 + 1) * 68 + row] = v.y;
            xs[(kq * 4 + 2) * 68 + row] = v.z;
            xs[(kq * 4 + 3) * 68 + row] = v.w;
        }
        __syncthreads();
        #pragma unroll
        for (int kk = 0; kk < 32; kk++) {
            float4 b = *(const float4*)&ws[(kc * 32 + kk) * NH + c0];
            float4 a = *(const float4*)&xs[kk * 68 + r0];
            unsigned long long a01 = pk2(a.x, a.y);
            unsigned long long a23 = pk2(a.z, a.w);
            unsigned long long b0 = pk2(b.x, b.x);
            unsigned long long b1 = pk2(b.y, b.y);
            unsigned long long b2 = pk2(b.z, b.z);
            unsigned long long b3 = pk2(b.w, b.w);
            fma2(acc[0][0], a01, b0); fma2(acc[1][0], a23, b0);
            fma2(acc[0][1], a01, b1); fma2(acc[1][1], a23, b1);
            fma2(acc[0][2], a01, b2); fma2(acc[1][2], a23, b2);
            fma2(acc[0][3], a01, b3); fma2(acc[1][3], a23, b3);
        }
    }

    #pragma unroll
    for (int rp = 0; rp < 2; rp++) {
        float2 c0v = upk2(acc[rp][0]);
        float2 c1v = upk2(acc[rp][1]);
        float2 c2v = upk2(acc[rp][2]);
        float2 c3v = upk2(acc[rp][3]);
        int gr0 = row0 + r0 + 2 * rp;
        if (gr0 < n) {
            __half2 h01 = __floats2half2_rn(c0v.x, c1v.x);
            __half2 h23 = __floats2half2_rn(c2v.x, c3v.x);
            *(uint2*)&g_h0h[gr0 * NH + c0] = make_uint2(h2_to_u(h01), h2_to_u(h23));
        }
        if (gr0 + 1 < n) {
            __half2 h01 = __floats2half2_rn(c0v.y, c1v.y);
            __half2 h23 = __floats2half2_rn(c2v.y, c3v.y);
            *(uint2*)&g_h0h[(gr0 + 1) * NH + c0] = make_uint2(h2_to_u(h01), h2_to_u(h23));
        }
    }
}

// ---------------------------------------------------------------------------
// Scatter1: g_h1[dst] += h0h[src] * w.
// 16 lanes per edge (R3 geometry), lane: 1 LDG.64 (4 halves) + 1 RED.v4.f32.
// 96 edges per 256-thread block, 6 edges per thread (MLP=6).
// ---------------------------------------------------------------------------
__global__ void __launch_bounds__(256) scatter1_kernel(
    const int* __restrict__ ei, const float* __restrict__ ew, int E)
{
    __shared__ int   ssrc[96];
    __shared__ int   sdst[96];
    __shared__ float sw[96];

    int tid = threadIdx.x;
    int ebase = blockIdx.x * 96;
    if (tid < 96) {
        int e = ebase + tid;
        ssrc[tid] = (e < E) ? __ldg(&ei[e]) : -1;
        sw[tid]   = (e < E) ? __ldg(&ew[e]) : 0.f;
    } else if (tid < 192) {
        int e = ebase + (tid - 96);
        sdst[tid - 96] = (e < E) ? __ldg(&ei[E + e]) : 0;
    }
    __syncthreads();

    int g = tid >> 4;          // edge-slot 0..15
    int q = tid & 15;          // feature quad 0..15

    int   s[6], d[6];
    float w[6];
    uint2 raw[6];

    #pragma unroll
    for (int u = 0; u < 6; u++) {
        int le = g + u * 16;
        s[u] = ssrc[le];
        d[u] = sdst[le];
        w[u] = sw[le];
    }
    #pragma unroll
    for (int u = 0; u < 6; u++) {
        raw[u] = make_uint2(0, 0);
        if (s[u] >= 0)
            raw[u] = __ldg((const uint2*)(g_h0h + s[u] * NH + q * 4));
    }
    #pragma unroll
    for (int u = 0; u < 6; u++) {
        if (s[u] < 0) continue;
        float wt = w[u];
        float2 f0 = __half22float2(u_to_h2(raw[u].x));
        float2 f1 = __half22float2(u_to_h2(raw[u].y));
        asm volatile("red.global.add.v4.f32 [%0], {%1,%2,%3,%4};"
                     :: "l"(&g_h1[d[u] * NH + q * 4]),
                        "f"(f0.x * wt), "f"(f0.y * wt),
                        "f"(f1.x * wt), "f"(f1.y * wt)
                     : "memory");
    }
}

// ---------------------------------------------------------------------------
// GEMM2: h2 = relu(h1) @ W2 (fp32 math), store fp16; zeroes d_out rows.
// ---------------------------------------------------------------------------
__global__ void __launch_bounds__(256) gemm2_kernel(
    const float* __restrict__ W2, float* __restrict__ out, int n)
{
    __shared__ float ws[NH * NC];
    __shared__ float hs[64 * 65];

    int tid = threadIdx.x;
    #pragma unroll
    for (int i = tid; i < NH * NC / 4; i += 256)
        ((float4*)ws)[i] = ((const float4*)W2)[i];

    int row0 = blockIdx.x * 64;
    #pragma unroll
    for (int idx = tid; idx < 64 * 64; idx += 256) {
        int r = idx >> 6, k = idx & 63;
        int grow = row0 + r;
        float v = 0.f;
        if (grow < n) v = g_h1[grow * NH + k];
        hs[r * 65 + k] = fmaxf(v, 0.f);   // fused ReLU
    }
    __syncthreads();

    int cg = tid & 3, r = tid >> 2;
    float a0 = 0.f, a1 = 0.f, a2 = 0.f, a3 = 0.f;
    #pragma unroll
    for (int k = 0; k < NH; k++) {
        float a = hs[r * 65 + k];
        float4 b = *(const float4*)&ws[k * NC + cg * 4];
        a0 += a * b.x; a1 += a * b.y; a2 += a * b.z; a3 += a * b.w;
    }

    int grow = row0 + r;
    if (grow < n) {
        __half2 h01 = __floats2half2_rn(a0, a1);
        __half2 h23 = __floats2half2_rn(a2, a3);
        *(uint2*)&g_h2h[grow * NC + cg * 4] = make_uint2(h2_to_u(h01), h2_to_u(h23));
        *(float4*)&out[grow * NC + cg * 4] = make_float4(0.f, 0.f, 0.f, 0.f);
    }
}

// ---------------------------------------------------------------------------
// Scatter2: out[dst] += h2h[src] * w.
// 4 lanes per edge (R4 geometry), lane: 1 LDG.64 (4 halves) + 1 RED.v4.f32.
// 512 edges per 256-thread block, 8 edges per thread (MLP=8).
// ---------------------------------------------------------------------------
__global__ void __launch_bounds__(256) scatter2_kernel(
    const int* __restrict__ ei, const float* __restrict__ ew,
    float* __restrict__ out, int E)
{
    __shared__ int   ssrc[512];
    __shared__ int   sdst[512];
    __shared__ float sw[512];

    int tid = threadIdx.x;
    int ebase = blockIdx.x * 512;
    #pragma unroll
    for (int i = tid; i < 512; i += 256) {
        int e = ebase + i;
        ssrc[i] = (e < E) ? __ldg(&ei[e]) : -1;
        sdst[i] = (e < E) ? __ldg(&ei[E + e]) : 0;
        sw[i]   = (e < E) ? __ldg(&ew[e]) : 0.f;
    }
    __syncthreads();

    int g = tid >> 2;          // edge-slot 0..63
    int q = tid & 3;           // feature quad 0..3

    int   s[8], d[8];
    float w[8];
    uint2 raw[8];

    #pragma unroll
    for (int u = 0; u < 8; u++) {
        int le = g + u * 64;
        s[u] = ssrc[le];
        d[u] = sdst[le];
        w[u] = sw[le];
    }
    #pragma unroll
    for (int u = 0; u < 8; u++) {
        raw[u] = make_uint2(0, 0);
        if (s[u] >= 0)
            raw[u] = __ldg((const uint2*)(g_h2h + s[u] * NC + q * 4));
    }
    #pragma unroll
    for (int u = 0; u < 8; u++) {
        if (s[u] < 0) continue;
        float wt = w[u];
        float2 f0 = __half22float2(u_to_h2(raw[u].x));
        float2 f1 = __half22float2(u_to_h2(raw[u].y));
        asm volatile("red.global.add.v4.f32 [%0], {%1,%2,%3,%4};"
                     :: "l"(&out[d[u] * NC + q * 4]),
                        "f"(f0.x * wt), "f"(f0.y * wt),
                        "f"(f1.x * wt), "f"(f1.y * wt)
                     : "memory");
    }
}

// ---------------------------------------------------------------------------
extern "C" void kernel_launch(void* const* d_in, const int* in_sizes, int n_in,
                              void* d_out, int out_size)
{
    const float* x   = (const float*)d_in[0];
    const int*   ei1 = (const int*)  d_in[1];
    const int*   ei2 = (const int*)  d_in[2];
    const float* ew1 = (const float*)d_in[3];
    const float* ew2 = (const float*)d_in[4];
    const float* W1  = (const float*)d_in[5];
    const float* W2  = (const float*)d_in[6];
    float* out = (float*)d_out;

    int n  = in_sizes[0] / NF;
    int E1 = in_sizes[3];
    int E2 = in_sizes[4];
    int nb = (n + 63) / 64;

    gemm1_kernel<<<nb, 256>>>(x, W1, n);                       // writes h0h, zeroes g_h1
    scatter1_kernel<<<(E1 + 95) / 96, 256>>>(ei1, ew1, E1);
    gemm2_kernel<<<nb, 256>>>(W2, out, n);                     // writes h2h, zeroes out
    scatter2_kernel<<<(E2 + 511) / 512, 256>>>(ei2, ew2, out, E2);
}

// round 13
// speedup vs baseline: 1.5307x; 1.5307x over previous
#include <cuda_runtime.h>
#include <cuda_bf16.h>

#define N_MAX 100000
#define NF 128
#define NH 64
#define NC 16

// Scratch (alloc-free rule: __device__ globals)
__device__ float g_h0[N_MAX * NH];   // x @ W1
__device__ float g_h1[N_MAX * NH];   // segment_sum layer 1 (accumulator)
__device__ float g_h2[N_MAX * NC];   // relu(h1) @ W2

// ---------------- packed f32x2 helpers -------------------------------------
__device__ __forceinline__ unsigned long long pk2(float lo, float hi) {
    unsigned long long r;
    asm("mov.b64 %0, {%1, %2};" : "=l"(r) : "f"(lo), "f"(hi));
    return r;
}
__device__ __forceinline__ void fma2(unsigned long long& d,
                                     unsigned long long a, unsigned long long b) {
    asm("fma.rn.f32x2 %0, %1, %2, %0;" : "+l"(d) : "l"(a), "l"(b));
}
__device__ __forceinline__ float2 upk2(unsigned long long v) {
    float2 f;
    asm("mov.b64 {%0, %1}, %2;" : "=f"(f.x), "=f"(f.y) : "l"(v));
    return f;
}

// ---------------------------------------------------------------------------
// GEMM1: h0[n,64] = x[n,128] @ W1[128,64] via packed fma.rn.f32x2 (FFMA2).
// fp32 in/out (bit-identical rounding to scalar FFMA). Zeroes g_h1 rows.
// Block: 256 threads, tile 64x64, per-thread 4 rows (2 f32x2 pairs) x 4 cols.
// ---------------------------------------------------------------------------
__global__ void __launch_bounds__(256) gemm1_kernel(
    const float* __restrict__ x, const float* __restrict__ W1, int n)
{
    __shared__ float ws[NF * NH];    // [k][c], 32 KB
    __shared__ float xs[32 * 68];    // [k_local][row], stride 68 (16B-aligned)

    int tid = threadIdx.x;
    #pragma unroll
    for (int i = tid; i < NF * NH / 4; i += 256)
        ((float4*)ws)[i] = ((const float4*)W1)[i];

    int row0 = blockIdx.x * 64;
    int tx = tid & 15, ty = tid >> 4;
    int r0 = ty * 4, c0 = tx * 4;
    int kq = tid & 7;
    int lrow = tid >> 3;

    unsigned long long acc[2][4] = {};   // [rowpair][col]

    for (int kc = 0; kc < 4; kc++) {
        __syncthreads();
        #pragma unroll
        for (int pass = 0; pass < 2; pass++) {
            int row = lrow + pass * 32;
            int grow = row0 + row;
            float4 v = make_float4(0.f, 0.f, 0.f, 0.f);
            if (grow < n)
                v = *(const float4*)&x[grow * NF + kc * 32 + kq * 4];
            xs[(kq * 4 + 0) * 68 + row] = v.x;
            xs[(kq * 4 + 1) * 68 + row] = v.y;
            xs[(kq * 4 + 2) * 68 + row] = v.z;
            xs[(kq * 4 + 3) * 68 + row] = v.w;
        }
        __syncthreads();
        #pragma unroll
        for (int kk = 0; kk < 32; kk++) {
            float4 b = *(const float4*)&ws[(kc * 32 + kk) * NH + c0];
            float4 a = *(const float4*)&xs[kk * 68 + r0];
            unsigned long long a01 = pk2(a.x, a.y);
            unsigned long long a23 = pk2(a.z, a.w);
            unsigned long long b0 = pk2(b.x, b.x);
            unsigned long long b1 = pk2(b.y, b.y);
            unsigned long long b2 = pk2(b.z, b.z);
            unsigned long long b3 = pk2(b.w, b.w);
            fma2(acc[0][0], a01, b0); fma2(acc[1][0], a23, b0);
            fma2(acc[0][1], a01, b1); fma2(acc[1][1], a23, b1);
            fma2(acc[0][2], a01, b2); fma2(acc[1][2], a23, b2);
            fma2(acc[0][3], a01, b3); fma2(acc[1][3], a23, b3);
        }
    }

    #pragma unroll
    for (int rp = 0; rp < 2; rp++) {
        float2 c0v = upk2(acc[rp][0]);
        float2 c1v = upk2(acc[rp][1]);
        float2 c2v = upk2(acc[rp][2]);
        float2 c3v = upk2(acc[rp][3]);
        int gr0 = row0 + r0 + 2 * rp;
        if (gr0 < n) {
            *(float4*)&g_h0[gr0 * NH + c0] = make_float4(c0v.x, c1v.x, c2v.x, c3v.x);
            *(float4*)&g_h1[gr0 * NH + c0] = make_float4(0.f, 0.f, 0.f, 0.f);
        }
        if (gr0 + 1 < n) {
            *(float4*)&g_h0[(gr0 + 1) * NH + c0] = make_float4(c0v.y, c1v.y, c2v.y, c3v.y);
            *(float4*)&g_h1[(gr0 + 1) * NH + c0] = make_float4(0.f, 0.f, 0.f, 0.f);
        }
    }
}

// ---------------------------------------------------------------------------
// Scatter1: g_h1[dst] += g_h0[src] * w.  EXACT R4 config (166us run):
// 64 edges per 256-thread block, 16 lanes/edge, 4 edges/thread, MLP=4.
// ---------------------------------------------------------------------------
__global__ void __launch_bounds__(256) scatter1_kernel(
    const int* __restrict__ ei, const float* __restrict__ ew, int E)
{
    __shared__ int   ssrc[64];
    __shared__ int   sdst[64];
    __shared__ float sw[64];

    int tid = threadIdx.x;
    int ebase = blockIdx.x * 64;
    if (tid < 64) {
        int e = ebase + tid;
        ssrc[tid] = (e < E) ? __ldg(&ei[e]) : -1;
    } else if (tid < 128) {
        int e = ebase + (tid - 64);
        sdst[tid - 64] = (e < E) ? __ldg(&ei[E + e]) : 0;
    } else if (tid < 192) {
        int e = ebase + (tid - 128);
        sw[tid - 128] = (e < E) ? __ldg(&ew[e]) : 0.f;
    }
    __syncthreads();

    int g = tid >> 4;          // edge-slot 0..15
    int q = tid & 15;          // feature quad 0..15

    int   s[4], d[4];
    float w[4];
    float4 v[4];

    #pragma unroll
    for (int u = 0; u < 4; u++) {
        int le = g + u * 16;
        s[u] = ssrc[le];
        d[u] = sdst[le];
        w[u] = sw[le];
    }
    #pragma unroll
    for (int u = 0; u < 4; u++) {
        v[u] = make_float4(0.f, 0.f, 0.f, 0.f);
        if (s[u] >= 0)
            v[u] = __ldg((const float4*)&g_h0[s[u] * NH + q * 4]);
    }
    #pragma unroll
    for (int u = 0; u < 4; u++) {
        if (s[u] >= 0) {
            float wt = w[u];
            asm volatile("red.global.add.v4.f32 [%0], {%1,%2,%3,%4};"
                         :: "l"(&g_h1[d[u] * NH + q * 4]),
                            "f"(v[u].x * wt), "f"(v[u].y * wt),
                            "f"(v[u].z * wt), "f"(v[u].w * wt)
                         : "memory");
        }
    }
}

// ---------------------------------------------------------------------------
// GEMM2: h2[n,16] = relu(h1[n,64]) @ W2[64,16]; also zeroes d_out rows.
// ---------------------------------------------------------------------------
__global__ void __launch_bounds__(256) gemm2_kernel(
    const float* __restrict__ W2, float* __restrict__ out, int n)
{
    __shared__ float ws[NH * NC];
    __shared__ float hs[64 * 65];

    int tid = threadIdx.x;
    #pragma unroll
    for (int i = tid; i < NH * NC / 4; i += 256)
        ((float4*)ws)[i] = ((const float4*)W2)[i];

    int row0 = blockIdx.x * 64;
    #pragma unroll
    for (int idx = tid; idx < 64 * 64; idx += 256) {
        int r = idx >> 6, k = idx & 63;
        int grow = row0 + r;
        float v = 0.f;
        if (grow < n) v = g_h1[grow * NH + k];
        hs[r * 65 + k] = fmaxf(v, 0.f);   // fused ReLU
    }
    __syncthreads();

    int cg = tid & 3, r = tid >> 2;
    float a0 = 0.f, a1 = 0.f, a2 = 0.f, a3 = 0.f;
    #pragma unroll
    for (int k = 0; k < NH; k++) {
        float a = hs[r * 65 + k];
        float4 b = *(const float4*)&ws[k * NC + cg * 4];
        a0 += a * b.x; a1 += a * b.y; a2 += a * b.z; a3 += a * b.w;
    }

    int grow = row0 + r;
    if (grow < n) {
        *(float4*)&g_h2[grow * NC + cg * 4] = make_float4(a0, a1, a2, a3);
        *(float4*)&out[grow * NC + cg * 4]  = make_float4(0.f, 0.f, 0.f, 0.f);
    }
}

// ---------------------------------------------------------------------------
// Scatter2: out[dst] += g_h2[src] * w.  EXACT R4 config:
// 256 edges per 256-thread block, 4 lanes/edge, 4 edges/thread, MLP=4.
// ---------------------------------------------------------------------------
__global__ void __launch_bounds__(256) scatter2_kernel(
    const int* __restrict__ ei, const float* __restrict__ ew,
    float* __restrict__ out, int E)
{
    __shared__ int   ssrc[256];
    __shared__ int   sdst[256];
    __shared__ float sw[256];

    int tid = threadIdx.x;
    int ebase = blockIdx.x * 256;
    {
        int e = ebase + tid;
        ssrc[tid] = (e < E) ? __ldg(&ei[e]) : -1;
        sdst[tid] = (e < E) ? __ldg(&ei[E + e]) : 0;
        sw[tid]   = (e < E) ? __ldg(&ew[e]) : 0.f;
    }
    __syncthreads();

    int g = tid >> 2;          // edge-slot 0..63
    int q = tid & 3;           // feature quad 0..3

    int   s[4], d[4];
    float w[4];
    float4 v[4];

    #pragma unroll
    for (int u = 0; u < 4; u++) {
        int le = g + u * 64;
        s[u] = ssrc[le];
        d[u] = sdst[le];
        w[u] = sw[le];
    }
    #pragma unroll
    for (int u = 0; u < 4; u++) {
        v[u] = make_float4(0.f, 0.f, 0.f, 0.f);
        if (s[u] >= 0)
            v[u] = __ldg((const float4*)&g_h2[s[u] * NC + q * 4]);
    }
    #pragma unroll
    for (int u = 0; u < 4; u++) {
        if (s[u] >= 0) {
            float wt = w[u];
            asm volatile("red.global.add.v4.f32 [%0], {%1,%2,%3,%4};"
                         :: "l"(&out[d[u] * NC + q * 4]),
                            "f"(v[u].x * wt), "f"(v[u].y * wt),
                            "f"(v[u].z * wt), "f"(v[u].w * wt)
                         : "memory");
        }
    }
}

// ---------------------------------------------------------------------------
extern "C" void kernel_launch(void* const* d_in, const int* in_sizes, int n_in,
                              void* d_out, int out_size)
{
    const float* x   = (const float*)d_in[0];
    const int*   ei1 = (const int*)  d_in[1];
    const int*   ei2 = (const int*)  d_in[2];
    const float* ew1 = (const float*)d_in[3];
    const float* ew2 = (const float*)d_in[4];
    const float* W1  = (const float*)d_in[5];
    const float* W2  = (const float*)d_in[6];
    float* out = (float*)d_out;

    int n  = in_sizes[0] / NF;
    int E1 = in_sizes[3];
    int E2 = in_sizes[4];
    int nb = (n + 63) / 64;

    gemm1_kernel<<<nb, 256>>>(x, W1, n);                       // writes h0, zeroes g_h1
    scatter1_kernel<<<(E1 + 63) / 64, 256>>>(ei1, ew1, E1);
    gemm2_kernel<<<nb, 256>>>(W2, out, n);                     // writes h2, zeroes out
    scatter2_kernel<<<(E2 + 255) / 256, 256>>>(ei2, ew2, out, E2);
}

// round 14
// speedup vs baseline: 1.6022x; 1.0467x over previous
#include <cuda_runtime.h>
#include <cuda_bf16.h>
#include <cuda_fp16.h>

#define N_MAX 100000
#define NF 128
#define NH 64
#define NC 16

// Scratch (alloc-free rule: __device__ globals)
__device__ __half g_h0h[N_MAX * NH];   // x @ W1, fp16
__device__ float  g_h1[N_MAX * NH];    // layer-1 aggregate, fp32
__device__ __half g_h2h[N_MAX * NC];   // relu(h1) @ W2, fp16

// ---------------- bit-cast helpers -----------------------------------------
__device__ __forceinline__ unsigned int h2_to_u(__half2 h) {
    unsigned int u; memcpy(&u, &h, 4); return u;
}
__device__ __forceinline__ __half2 u_to_h2(unsigned int u) {
    __half2 h; memcpy(&h, &u, 4); return h;
}

// ---------------- packed f32x2 helpers -------------------------------------
__device__ __forceinline__ unsigned long long pk2(float lo, float hi) {
    unsigned long long r;
    asm("mov.b64 %0, {%1, %2};" : "=l"(r) : "f"(lo), "f"(hi));
    return r;
}
__device__ __forceinline__ void fma2(unsigned long long& d,
                                     unsigned long long a, unsigned long long b) {
    asm("fma.rn.f32x2 %0, %1, %2, %0;" : "+l"(d) : "l"(a), "l"(b));
}
__device__ __forceinline__ float2 upk2(unsigned long long v) {
    float2 f;
    asm("mov.b64 {%0, %1}, %2;" : "=f"(f.x), "=f"(f.y) : "l"(v));
    return f;
}

// ---------------------------------------------------------------------------
// GEMM1: h0 = x @ W1 (fp32 math, FFMA2), stored fp16. Zeroes g_h1 rows.
// ---------------------------------------------------------------------------
__global__ void __launch_bounds__(256) gemm1_kernel(
    const float* __restrict__ x, const float* __restrict__ W1, int n)
{
    __shared__ float ws[NF * NH];    // [k][c], 32 KB
    __shared__ float xs[32 * 68];    // [k_local][row]

    int tid = threadIdx.x;
    #pragma unroll
    for (int i = tid; i < NF * NH / 4; i += 256)
        ((float4*)ws)[i] = ((const float4*)W1)[i];

    int row0 = blockIdx.x * 64;
    int tx = tid & 15, ty = tid >> 4;
    int r0 = ty * 4, c0 = tx * 4;
    int kq = tid & 7;
    int lrow = tid >> 3;

    unsigned long long acc[2][4] = {};   // [rowpair][col]

    for (int kc = 0; kc < 4; kc++) {
        __syncthreads();
        #pragma unroll
        for (int pass = 0; pass < 2; pass++) {
            int row = lrow + pass * 32;
            int grow = row0 + row;
            float4 v = make_float4(0.f, 0.f, 0.f, 0.f);
            if (grow < n)
                v = *(const float4*)&x[grow * NF + kc * 32 + kq * 4];
            xs[(kq * 4 + 0) * 68 + row] = v.x;
            xs[(kq * 4 + 1) * 68 + row] = v.y;
            xs[(kq * 4 + 2) * 68 + row] = v.z;
            xs[(kq * 4 + 3) * 68 + row] = v.w;
        }
        __syncthreads();
        #pragma unroll
        for (int kk = 0; kk < 32; kk++) {
            float4 b = *(const float4*)&ws[(kc * 32 + kk) * NH + c0];
            float4 a = *(const float4*)&xs[kk * 68 + r0];
            unsigned long long a01 = pk2(a.x, a.y);
            unsigned long long a23 = pk2(a.z, a.w);
            unsigned long long b0 = pk2(b.x, b.x);
            unsigned long long b1 = pk2(b.y, b.y);
            unsigned long long b2 = pk2(b.z, b.z);
            unsigned long long b3 = pk2(b.w, b.w);
            fma2(acc[0][0], a01, b0); fma2(acc[1][0], a23, b0);
            fma2(acc[0][1], a01, b1); fma2(acc[1][1], a23, b1);
            fma2(acc[0][2], a01, b2); fma2(acc[1][2], a23, b2);
            fma2(acc[0][3], a01, b3); fma2(acc[1][3], a23, b3);
        }
    }

    #pragma unroll
    for (int rp = 0; rp < 2; rp++) {
        float2 c0v = upk2(acc[rp][0]);
        float2 c1v = upk2(acc[rp][1]);
        float2 c2v = upk2(acc[rp][2]);
        float2 c3v = upk2(acc[rp][3]);
        int gr0 = row0 + r0 + 2 * rp;
        if (gr0 < n) {
            __half2 h01 = __floats2half2_rn(c0v.x, c1v.x);
            __half2 h23 = __floats2half2_rn(c2v.x, c3v.x);
            *(uint2*)&g_h0h[gr0 * NH + c0] = make_uint2(h2_to_u(h01), h2_to_u(h23));
            *(float4*)&g_h1[gr0 * NH + c0] = make_float4(0.f, 0.f, 0.f, 0.f);
        }
        if (gr0 + 1 < n) {
            __half2 h01 = __floats2half2_rn(c0v.y, c1v.y);
            __half2 h23 = __floats2half2_rn(c2v.y, c3v.y);
            *(uint2*)&g_h0h[(gr0 + 1) * NH + c0] = make_uint2(h2_to_u(h01), h2_to_u(h23));
            *(float4*)&g_h1[(gr0 + 1) * NH + c0] = make_float4(0.f, 0.f, 0.f, 0.f);
        }
    }
}

// ---------------------------------------------------------------------------
// Scatter1: g_h1[dst] += h0h[src] * w.  EXACT R4 geometry:
// 64 edges/block, 16 lanes/edge, 4 edges/thread, MLP=4.
// Only change vs R4: lane gather is LDG.64 of 4 fp16 (was LDG.128 of 4 fp32).
// ---------------------------------------------------------------------------
__global__ void __launch_bounds__(256) scatter1_kernel(
    const int* __restrict__ ei, const float* __restrict__ ew, int E)
{
    __shared__ int   ssrc[64];
    __shared__ int   sdst[64];
    __shared__ float sw[64];

    int tid = threadIdx.x;
    int ebase = blockIdx.x * 64;
    if (tid < 64) {
        int e = ebase + tid;
        ssrc[tid] = (e < E) ? __ldg(&ei[e]) : -1;
    } else if (tid < 128) {
        int e = ebase + (tid - 64);
        sdst[tid - 64] = (e < E) ? __ldg(&ei[E + e]) : 0;
    } else if (tid < 192) {
        int e = ebase + (tid - 128);
        sw[tid - 128] = (e < E) ? __ldg(&ew[e]) : 0.f;
    }
    __syncthreads();

    int g = tid >> 4;          // edge-slot 0..15
    int q = tid & 15;          // feature quad 0..15

    int   s[4], d[4];
    float w[4];
    uint2 raw[4];

    #pragma unroll
    for (int u = 0; u < 4; u++) {
        int le = g + u * 16;
        s[u] = ssrc[le];
        d[u] = sdst[le];
        w[u] = sw[le];
    }
    #pragma unroll
    for (int u = 0; u < 4; u++) {
        raw[u] = make_uint2(0, 0);
        if (s[u] >= 0)
            raw[u] = __ldg((const uint2*)(g_h0h + s[u] * NH + q * 4));
    }
    #pragma unroll
    for (int u = 0; u < 4; u++) {
        if (s[u] >= 0) {
            float wt = w[u];
            float2 f0 = __half22float2(u_to_h2(raw[u].x));
            float2 f1 = __half22float2(u_to_h2(raw[u].y));
            asm volatile("red.global.add.v4.f32 [%0], {%1,%2,%3,%4};"
                         :: "l"(&g_h1[d[u] * NH + q * 4]),
                            "f"(f0.x * wt), "f"(f0.y * wt),
                            "f"(f1.x * wt), "f"(f1.y * wt)
                         : "memory");
        }
    }
}

// ---------------------------------------------------------------------------
// GEMM2: h2 = relu(h1) @ W2 (fp32 math), stored fp16; zeroes d_out rows.
// ---------------------------------------------------------------------------
__global__ void __launch_bounds__(256) gemm2_kernel(
    const float* __restrict__ W2, float* __restrict__ out, int n)
{
    __shared__ float ws[NH * NC];
    __shared__ float hs[64 * 65];

    int tid = threadIdx.x;
    #pragma unroll
    for (int i = tid; i < NH * NC / 4; i += 256)
        ((float4*)ws)[i] = ((const float4*)W2)[i];

    int row0 = blockIdx.x * 64;
    #pragma unroll
    for (int idx = tid; idx < 64 * 64; idx += 256) {
        int r = idx >> 6, k = idx & 63;
        int grow = row0 + r;
        float v = 0.f;
        if (grow < n) v = g_h1[grow * NH + k];
        hs[r * 65 + k] = fmaxf(v, 0.f);   // fused ReLU
    }
    __syncthreads();

    int cg = tid & 3, r = tid >> 2;
    float a0 = 0.f, a1 = 0.f, a2 = 0.f, a3 = 0.f;
    #pragma unroll
    for (int k = 0; k < NH; k++) {
        float a = hs[r * 65 + k];
        float4 b = *(const float4*)&ws[k * NC + cg * 4];
        a0 += a * b.x; a1 += a * b.y; a2 += a * b.z; a3 += a * b.w;
    }

    int grow = row0 + r;
    if (grow < n) {
        __half2 h01 = __floats2half2_rn(a0, a1);
        __half2 h23 = __floats2half2_rn(a2, a3);
        *(uint2*)&g_h2h[grow * NC + cg * 4] = make_uint2(h2_to_u(h01), h2_to_u(h23));
        *(float4*)&out[grow * NC + cg * 4]  = make_float4(0.f, 0.f, 0.f, 0.f);
    }
}

// ---------------------------------------------------------------------------
// Scatter2: out[dst] += h2h[src] * w.  EXACT R4 geometry:
// 256 edges/block, 4 lanes/edge, 4 edges/thread, MLP=4.
// Only change vs R4: lane gather is LDG.64 of 4 fp16.
// ---------------------------------------------------------------------------
__global__ void __launch_bounds__(256) scatter2_kernel(
    const int* __restrict__ ei, const float* __restrict__ ew,
    float* __restrict__ out, int E)
{
    __shared__ int   ssrc[256];
    __shared__ int   sdst[256];
    __shared__ float sw[256];

    int tid = threadIdx.x;
    int ebase = blockIdx.x * 256;
    {
        int e = ebase + tid;
        ssrc[tid] = (e < E) ? __ldg(&ei[e]) : -1;
        sdst[tid] = (e < E) ? __ldg(&ei[E + e]) : 0;
        sw[tid]   = (e < E) ? __ldg(&ew[e]) : 0.f;
    }
    __syncthreads();

    int g = tid >> 2;          // edge-slot 0..63
    int q = tid & 3;           // feature quad 0..3

    int   s[4], d[4];
    float w[4];
    uint2 raw[4];

    #pragma unroll
    for (int u = 0; u < 4; u++) {
        int le = g + u * 64;
        s[u] = ssrc[le];
        d[u] = sdst[le];
        w[u] = sw[le];
    }
    #pragma unroll
    for (int u = 0; u < 4; u++) {
        raw[u] = make_uint2(0, 0);
        if (s[u] >= 0)
            raw[u] = __ldg((const uint2*)(g_h2h + s[u] * NC + q * 4));
    }
    #pragma unroll
    for (int u = 0; u < 4; u++) {
        if (s[u] >= 0) {
            float wt = w[u];
            float2 f0 = __half22float2(u_to_h2(raw[u].x));
            float2 f1 = __half22float2(u_to_h2(raw[u].y));
            asm volatile("red.global.add.v4.f32 [%0], {%1,%2,%3,%4};"
                         :: "l"(&out[d[u] * NC + q * 4]),
                            "f"(f0.x * wt), "f"(f0.y * wt),
                            "f"(f1.x * wt), "f"(f1.y * wt)
                         : "memory");
        }
    }
}

// ---------------------------------------------------------------------------
extern "C" void kernel_launch(void* const* d_in, const int* in_sizes, int n_in,
                              void* d_out, int out_size)
{
    const float* x   = (const float*)d_in[0];
    const int*   ei1 = (const int*)  d_in[1];
    const int*   ei2 = (const int*)  d_in[2];
    const float* ew1 = (const float*)d_in[3];
    const float* ew2 = (const float*)d_in[4];
    const float* W1  = (const float*)d_in[5];
    const float* W2  = (const float*)d_in[6];
    float* out = (float*)d_out;

    int n  = in_sizes[0] / NF;
    int E1 = in_sizes[3];
    int E2 = in_sizes[4];
    int nb = (n + 63) / 64;

    gemm1_kernel<<<nb, 256>>>(x, W1, n);                       // writes h0h, zeroes g_h1
    scatter1_kernel<<<(E1 + 63) / 64, 256>>>(ei1, ew1, E1);
    gemm2_kernel<<<nb, 256>>>(W2, out, n);                     // writes h2h, zeroes out
    scatter2_kernel<<<(E2 + 255) / 256, 256>>>(ei2, ew2, out, E2);
}